// round 2
// baseline (speedup 1.0000x reference)
#include <cuda_runtime.h>
#include <cuda_bf16.h>
#include <math.h>

// Problem constants
#define BB 32
#define PP 64
#define LL 64
#define VV 32000

// Scratch (__device__ globals — no allocation allowed)
__device__ int   g_len[BB];
__device__ int   g_m[BB * PP];
__device__ int   g_hit[BB * PP * LL];
__device__ float g_loss[BB * PP];

// ---------------------------------------------------------------------------
// Kernel 0: decode mask -> lengths. Mask dtype is sniffed from the first word
// (lengths >= L/2 = 32, so mask[0..3] are all true).
// ---------------------------------------------------------------------------
__global__ void prep_kernel(const void* __restrict__ mask) {
    __shared__ int mode;
    int tid = threadIdx.x;
    if (tid == 0) {
        unsigned w = *(const unsigned*)mask;
        if (w == 0x01010101u)      mode = 0;  // 1-byte bool
        else if (w == 0x3F800000u) mode = 2;  // float32
        else if (w == 0x3F803F80u) mode = 3;  // bf16
        else                       mode = 1;  // int32 (w == 1)
    }
    __syncthreads();
    if (tid < BB) {
        int cnt = 0;
        if (mode == 0) {
            const unsigned char* p = (const unsigned char*)mask + tid * LL;
            for (int j = 0; j < LL; j++) cnt += (p[j] != 0);
        } else if (mode == 1) {
            const int* p = (const int*)mask + tid * LL;
            for (int j = 0; j < LL; j++) cnt += (p[j] != 0);
        } else if (mode == 2) {
            const float* p = (const float*)mask + tid * LL;
            for (int j = 0; j < LL; j++) cnt += (p[j] != 0.0f);
        } else {
            const unsigned short* p = (const unsigned short*)mask + tid * LL;
            for (int j = 0; j < LL; j++) cnt += (p[j] != 0);
        }
        g_len[tid] = cnt;
    }
}

// ---------------------------------------------------------------------------
// Kernel 1: edit-distance DP + argmin hit-set per (b, i).
// One block per batch, 64 threads (one per target column j).
// Row recurrence with min-plus prefix scan exactly matching the reference.
// All DP values are exact small integers in fp32 -> equality test is robust.
// ---------------------------------------------------------------------------
__global__ void dp_kernel(const int* __restrict__ syms,
                          const int* __restrict__ targets) {
    const int b = blockIdx.x;
    const int j = threadIdx.x;                 // 0..63
    __shared__ float sh[64];
    __shared__ int   targ[64];
    __shared__ int   cands[64];

    const int len = g_len[b];
    targ[j] = targets[b * LL + j];
    __syncthreads();

    float prev = (float)j;                     // row 0: dist = j
    if (j == 0) {                              // row 0: min over j<len of j is 0 at j=0
        g_m[b * PP] = 1;
        g_hit[(b * PP) * LL] = targ[0];
    }
    const int lane = j & 31;
    const int w    = j >> 5;

    for (int i = 1; i < PP; i++) {
        int sym = syms[b * PP + (i - 1)];
        sh[j] = prev;
        __syncthreads();
        float tmp;
        if (j == 0) tmp = (float)i;
        else        tmp = fminf(sh[j - 1] + ((sym != targ[j - 1]) ? 1.0f : 0.0f),
                                prev + 1.0f);
        __syncthreads();

        // cur[j] = j + cummin_{k<=j}(tmp[k] - k): inclusive min-scan over 64
        float s = tmp - (float)j;
        #pragma unroll
        for (int off = 1; off < 32; off <<= 1) {
            float o = __shfl_up_sync(0xffffffffu, s, off);
            if (lane >= off) s = fminf(s, o);
        }
        if (lane == 31) sh[w] = s;
        __syncthreads();
        if (w == 1) s = fminf(s, sh[0]);
        float cur = s + (float)j;

        // masked block-min
        float v = (j < len) ? cur : 3.0e38f;
        float r = v;
        #pragma unroll
        for (int off = 16; off; off >>= 1)
            r = fminf(r, __shfl_xor_sync(0xffffffffu, r, off));
        __syncthreads();
        if (lane == 0) sh[w] = r;
        __syncthreads();
        float minv = fminf(sh[0], sh[1]);

        cands[j] = (j < len && v == minv) ? targ[j] : -1;
        __syncthreads();

        if (j == 0) {   // serial dedup of <=64 candidates (deterministic, tiny)
            int m = 0;
            int base = (b * PP + i) * LL;
            for (int k = 0; k < LL; k++) {
                int c = cands[k];
                if (c < 0) continue;
                bool dup = false;
                for (int t = 0; t < m; t++)
                    if (g_hit[base + t] == c) { dup = true; break; }
                if (!dup) g_hit[base + (m++)] = c;
            }
            g_m[b * PP + i] = m;
        }
        prev = cur;
        __syncthreads();
    }
}

// ---------------------------------------------------------------------------
// Kernel 2: the HBM-bound part. One block per (b,i): S_all = row-sum over V,
// S_hit = gather over the hit set, then the closed-form two-value-softmax KL.
// Rows masked out (i >= len[b]) are skipped entirely -> ~24% less DRAM.
// ---------------------------------------------------------------------------
__global__ void __launch_bounds__(256)
reduce_kernel(const float* __restrict__ outputs) {
    const int blk = blockIdx.x;                // 0..2047
    const int b = blk >> 6, i = blk & 63;
    const int tid = threadIdx.x;
    __shared__ float sh_hit[64];
    __shared__ float sw[8];

    if (i >= g_len[b]) {
        if (tid == 0) g_loss[blk] = 0.0f;
        return;
    }

    const float* row = outputs + (size_t)blk * VV;
    const int m = g_m[blk];
    if (tid < 64) sh_hit[tid] = (tid < m) ? row[g_hit[blk * LL + tid]] : 0.0f;

    const float4* r4 = (const float4*)row;     // V = 32000 -> 8000 float4
    float acc = 0.0f;
    #pragma unroll 4
    for (int idx = tid; idx < VV / 4; idx += 256) {
        float4 v = __ldcs(r4 + idx);           // streaming: read-once data
        acc += (v.x + v.y) + (v.z + v.w);
    }
    #pragma unroll
    for (int off = 16; off; off >>= 1)
        acc += __shfl_xor_sync(0xffffffffu, acc, off);
    if ((tid & 31) == 0) sw[tid >> 5] = acc;
    __syncthreads();

    if (tid == 0) {
        float S_all = 0.0f;
        for (int k = 0; k < 8; k++) S_all += sw[k];
        float S_hit = 0.0f;
        for (int k = 0; k < m; k++) S_hit += sh_hit[k];

        const float em1 = 0.36787944117144233f;       // e^-1 (softmax shift)
        float fm = (float)m;
        float Z  = fm + ((float)VV - fm) * em1;
        float ph = 1.0f / Z;
        float pm = em1 / Z;
        float ent = fm * ph * logf(ph) + ((float)VV - fm) * pm * logf(pm);
        g_loss[blk] = ent - (pm * S_all + (ph - pm) * S_hit);
    }
}

// ---------------------------------------------------------------------------
// Kernel 3: deterministic final reduction -> scalar.
// ---------------------------------------------------------------------------
__global__ void final_kernel(float* __restrict__ out) {
    __shared__ float pb[BB];
    int b = threadIdx.x;
    if (b < BB) {
        float s = 0.0f;
        for (int i = 0; i < PP; i++) s += g_loss[b * PP + i];
        pb[b] = s / ((float)g_len[b] + 1e-13f);
    }
    __syncthreads();
    if (threadIdx.x == 0) {
        float s = 0.0f, n = 0.0f;
        for (int k = 0; k < BB; k++) {
            s += pb[k];
            if (g_len[k] > 0) n += 1.0f;
        }
        out[0] = s / (n + 1e-13f);
    }
}

// ---------------------------------------------------------------------------
extern "C" void kernel_launch(void* const* d_in, const int* in_sizes, int n_in,
                              void* d_out, int out_size) {
    const float* outputs = (const float*)d_in[0];   // (B,P,V) f32 log-probs
    const int*   syms    = (const int*)d_in[1];     // (B,P) i32
    const int*   targets = (const int*)d_in[2];     // (B,L) i32
    const void*  mask    = d_in[3];                 // (B,L) bool-ish

    prep_kernel<<<1, 32>>>(mask);
    dp_kernel<<<BB, 64>>>(syms, targets);
    reduce_kernel<<<BB * PP, 256>>>(outputs);
    final_kernel<<<1, 32>>>((float*)d_out);
}

// round 3
// speedup vs baseline: 34.3777x; 34.3777x over previous
#include <cuda_runtime.h>
#include <cuda_bf16.h>
#include <math.h>

// Problem constants
#define BB 32
#define PP 64
#define LL 64
#define VV 32000

// Scratch (__device__ globals — no allocation allowed)
__device__ int      g_len[BB];
__device__ unsigned g_mask32[BB * PP * 2];   // argmin bitmask, 2x u32 per (b,i)
__device__ float    g_loss[BB * PP];

// ---------------------------------------------------------------------------
// Kernel 0: decode mask -> lengths. Mask dtype sniffed from first 32-bit word
// (lengths >= L/2 = 32, so mask[0..3] are all true).
// ---------------------------------------------------------------------------
__global__ void prep_kernel(const void* __restrict__ mask) {
    __shared__ int mode;
    int tid = threadIdx.x;
    if (tid == 0) {
        unsigned w = *(const unsigned*)mask;
        if (w == 0x01010101u)      mode = 0;  // 1-byte bool
        else if (w == 0x3F800000u) mode = 2;  // float32
        else if (w == 0x3F803F80u) mode = 3;  // bf16
        else                       mode = 1;  // int32
    }
    __syncthreads();
    if (tid < BB) {
        int cnt = 0;
        if (mode == 0) {
            const unsigned char* p = (const unsigned char*)mask + tid * LL;
            for (int j = 0; j < LL; j++) cnt += (p[j] != 0);
        } else if (mode == 1) {
            const int* p = (const int*)mask + tid * LL;
            for (int j = 0; j < LL; j++) cnt += (p[j] != 0);
        } else if (mode == 2) {
            const float* p = (const float*)mask + tid * LL;
            for (int j = 0; j < LL; j++) cnt += (p[j] != 0.0f);
        } else {
            const unsigned short* p = (const unsigned short*)mask + tid * LL;
            for (int j = 0; j < LL; j++) cnt += (p[j] != 0);
        }
        g_len[tid] = cnt;
    }
}

// ---------------------------------------------------------------------------
// Kernel 1: edit-distance DP. One block per batch, 64 threads (one per j).
// Per row: min-plus prefix scan (matches reference), masked block-min, and a
// ballot of argmin positions -> two u32 stores. NO dedup here.
// ---------------------------------------------------------------------------
__global__ void dp_kernel(const int* __restrict__ syms,
                          const int* __restrict__ targets) {
    const int b = blockIdx.x;
    const int j = threadIdx.x;                 // 0..63
    __shared__ float sh[64];                   // prev row
    __shared__ float shc[2];                   // scan carry
    __shared__ float shm[2];                   // min partials
    __shared__ int   targ[64];

    const int len = g_len[b];
    targ[j] = targets[b * LL + j];
    const int lane = j & 31;
    const int w    = j >> 5;

    float prev = (float)j;                     // row 0: dist = j
    if (j == 0) {                              // row 0 argmin: only j=0 (dist 0)
        g_mask32[(b * PP) * 2 + 0] = 1u;
        g_mask32[(b * PP) * 2 + 1] = 0u;
    }
    __syncthreads();

    for (int i = 1; i < PP; i++) {
        int sym = syms[b * PP + (i - 1)];
        sh[j] = prev;
        __syncthreads();
        float tmp;
        if (j == 0) tmp = (float)i;
        else        tmp = fminf(sh[j - 1] + ((sym != targ[j - 1]) ? 1.0f : 0.0f),
                                prev + 1.0f);

        // cur[j] = j + cummin_{k<=j}(tmp[k] - k): inclusive min-scan over 64
        float s = tmp - (float)j;
        #pragma unroll
        for (int off = 1; off < 32; off <<= 1) {
            float o = __shfl_up_sync(0xffffffffu, s, off);
            if (lane >= off) s = fminf(s, o);
        }
        if (lane == 31) shc[w] = s;
        __syncthreads();
        if (w == 1) s = fminf(s, shc[0]);
        float cur = s + (float)j;

        // masked block-min
        float v = (j < len) ? cur : 3.0e38f;
        float r = v;
        #pragma unroll
        for (int off = 16; off; off >>= 1)
            r = fminf(r, __shfl_xor_sync(0xffffffffu, r, off));
        if (lane == 0) shm[w] = r;
        __syncthreads();
        float minv = fminf(shm[0], shm[1]);

        unsigned bal = __ballot_sync(0xffffffffu, (j < len) && (v == minv));
        if (lane == 0) g_mask32[(b * PP + i) * 2 + w] = bal;

        prev = cur;
        __syncthreads();
    }
}

// ---------------------------------------------------------------------------
// Kernel 2: HBM-bound. One block per (b,i). S_all = full-row sum (streamed),
// S_hit/m resolved from the argmin bitmask with shared-memory dedup — that
// work hides under the DRAM streaming.
// ---------------------------------------------------------------------------
__global__ void __launch_bounds__(256)
reduce_kernel(const float* __restrict__ outputs,
              const int* __restrict__ targets) {
    const int blk = blockIdx.x;                // 0..2047
    const int b = blk >> 6, i = blk & 63;
    const int tid = threadIdx.x;
    __shared__ int   targ[64];
    __shared__ float sw[8];
    __shared__ float sh_hv[2];
    __shared__ int   sh_fl[2];

    if (i >= g_len[b]) {
        if (tid == 0) g_loss[blk] = 0.0f;
        return;
    }

    const float* row = outputs + (size_t)blk * VV;

    if (tid < 64) targ[tid] = targets[b * LL + tid];
    __syncthreads();

    // hit resolution on first 64 threads (overlaps with streaming below)
    if (tid < 64) {
        unsigned lo = g_mask32[blk * 2 + 0];
        unsigned hi = g_mask32[blk * 2 + 1];
        int j = tid;
        bool hit = (j < 32) ? ((lo >> j) & 1u) : ((hi >> (j - 32)) & 1u);
        float val = 0.0f;
        int   flag = 0;
        if (hit) {
            int c = targ[j];
            bool first = true;
            for (int k = 0; k < j; k++) {
                bool hk = (k < 32) ? ((lo >> k) & 1u) : ((hi >> (k - 32)) & 1u);
                if (hk && targ[k] == c) { first = false; break; }
            }
            if (first) { val = row[c]; flag = 1; }
        }
        #pragma unroll
        for (int off = 16; off; off >>= 1) {
            val  += __shfl_xor_sync(0xffffffffu, val, off);
            flag += __shfl_xor_sync(0xffffffffu, flag, off);
        }
        if ((tid & 31) == 0) { sh_hv[tid >> 5] = val; sh_fl[tid >> 5] = flag; }
    }

    // streaming full-row sum
    const float4* r4 = (const float4*)row;     // V = 32000 -> 8000 float4
    float acc = 0.0f;
    #pragma unroll 4
    for (int idx = tid; idx < VV / 4; idx += 256) {
        float4 v = __ldcs(r4 + idx);
        acc += (v.x + v.y) + (v.z + v.w);
    }
    #pragma unroll
    for (int off = 16; off; off >>= 1)
        acc += __shfl_xor_sync(0xffffffffu, acc, off);
    if ((tid & 31) == 0) sw[tid >> 5] = acc;
    __syncthreads();

    if (tid == 0) {
        float S_all = 0.0f;
        for (int k = 0; k < 8; k++) S_all += sw[k];
        float S_hit = sh_hv[0] + sh_hv[1];
        int   m     = sh_fl[0] + sh_fl[1];

        const float em1 = 0.36787944117144233f;       // e^-1
        float fm = (float)m;
        float Z  = fm + ((float)VV - fm) * em1;
        float ph = 1.0f / Z;
        float pm = em1 / Z;
        float ent = fm * ph * logf(ph) + ((float)VV - fm) * pm * logf(pm);
        g_loss[blk] = ent - (pm * S_all + (ph - pm) * S_hit);
    }
}

// ---------------------------------------------------------------------------
// Kernel 3: deterministic final reduction -> scalar. 1024 threads.
// ---------------------------------------------------------------------------
__global__ void final_kernel(float* __restrict__ out) {
    __shared__ float pb[BB];
    int tid = threadIdx.x;
    int b = tid >> 5, lane = tid & 31;
    float s = g_loss[b * PP + lane] + g_loss[b * PP + 32 + lane];
    #pragma unroll
    for (int off = 16; off; off >>= 1)
        s += __shfl_xor_sync(0xffffffffu, s, off);
    if (lane == 0) pb[b] = s / ((float)g_len[b] + 1e-13f);
    __syncthreads();
    if (tid == 0) {
        float acc = 0.0f, n = 0.0f;
        for (int k = 0; k < BB; k++) {
            acc += pb[k];
            if (g_len[k] > 0) n += 1.0f;
        }
        out[0] = acc / (n + 1e-13f);
    }
}

// ---------------------------------------------------------------------------
extern "C" void kernel_launch(void* const* d_in, const int* in_sizes, int n_in,
                              void* d_out, int out_size) {
    const float* outputs = (const float*)d_in[0];   // (B,P,V) f32 log-probs
    const int*   syms    = (const int*)d_in[1];     // (B,P) i32
    const int*   targets = (const int*)d_in[2];     // (B,L) i32
    const void*  mask    = d_in[3];                 // (B,L) bool-ish

    prep_kernel<<<1, 32>>>(mask);
    dp_kernel<<<BB, 64>>>(syms, targets);
    reduce_kernel<<<BB * PP, 256>>>(outputs, targets);
    final_kernel<<<1, BB * 32>>>((float*)d_out);
}

// round 6
// speedup vs baseline: 43.2493x; 1.2581x over previous
#include <cuda_runtime.h>
#include <cuda_bf16.h>
#include <math.h>

#define BB 32
#define PP 64
#define LL 64
#define VV 32000
#define NROWS (BB * PP)          // 2048 reduce blocks
#define NBLK  (BB + NROWS)       // 32 dp blocks + 2048 reduce blocks

// Scratch (__device__ globals — no allocation allowed). Zero-init at load;
// the winner block resets mutable state at the end of every launch.
__device__ int      g_len[BB];
__device__ unsigned g_mask32[NROWS * 2];     // argmin bitmask per (b,i)
__device__ float    g_loss[NROWS];
__device__ volatile int g_dp_done[BB];
__device__ unsigned g_ctr;

// ---------------------------------------------------------------------------
__device__ __forceinline__ int mask_mode(const void* mask) {
    unsigned w = *(const unsigned*)mask;     // lengths >= 32 -> first 4 true
    if (w == 0x01010101u) return 0;          // 1-byte bool
    if (w == 0x3F800000u) return 2;          // float32
    if (w == 0x3F803F80u) return 3;          // bf16
    return 1;                                // int32
}
__device__ __forceinline__ bool mask_at(const void* mask, int mode, int idx) {
    if (mode == 0) return ((const unsigned char*)mask)[idx] != 0;
    if (mode == 1) return ((const int*)mask)[idx] != 0;
    if (mode == 2) return ((const float*)mask)[idx] != 0.0f;
    return ((const unsigned short*)mask)[idx] != 0;
}

// ---------------------------------------------------------------------------
// Single-warp edit-distance DP for batch b (2 columns per lane, no barriers).
// Row recurrence matches reference: tmp = min(diag + neq, ins + 1);
// cur[j] = j + cummin_{k<=j}(tmp[k] - k). Values are exact small ints in fp32.
// ---------------------------------------------------------------------------
__device__ void dp_warp(int b, const int* __restrict__ syms,
                        const int* __restrict__ targets,
                        const void* __restrict__ mask, int mode) {
    const unsigned FULL = 0xffffffffu;
    const int lane = threadIdx.x;            // 0..31
    const int j0 = lane, j1 = lane + 32;

    int t0 = targets[b * LL + j0];
    int t1 = targets[b * LL + j1];
    int tp0 = __shfl_up_sync(FULL, t0, 1);   // targ[j0-1] (lane>0)
    int tp1 = __shfl_up_sync(FULL, t1, 1);
    int t0_31 = __shfl_sync(FULL, t0, 31);
    if (lane == 0) tp1 = t0_31;              // targ[31]

    int s0 = syms[b * PP + j0];
    int s1 = syms[b * PP + j1];

    bool m0 = mask_at(mask, mode, b * LL + j0);
    bool m1 = mask_at(mask, mode, b * LL + j1);
    int len = __popc(__ballot_sync(FULL, m0)) + __popc(__ballot_sync(FULL, m1));
    if (lane == 0) g_len[b] = len;

    float prev0 = (float)j0, prev1 = (float)j1;   // row 0
    if (lane == 0) {                              // row 0 argmin: j=0 only
        g_mask32[(b * PP) * 2 + 0] = 1u;
        g_mask32[(b * PP) * 2 + 1] = 0u;
    }

    for (int i = 1; i < PP; i++) {
        int sa = __shfl_sync(FULL, s0, (i - 1) & 31);
        int sb = __shfl_sync(FULL, s1, (i - 1) & 31);
        int sym = (i <= 32) ? sa : sb;

        float d0 = __shfl_up_sync(FULL, prev0, 1);   // prev[j0-1]
        float d1 = __shfl_up_sync(FULL, prev1, 1);
        float p31 = __shfl_sync(FULL, prev0, 31);
        if (lane == 0) d1 = p31;

        float n0 = (sym != tp0) ? 1.0f : 0.0f;
        float n1 = (sym != tp1) ? 1.0f : 0.0f;
        float tmp0 = fminf(d0 + n0, prev0 + 1.0f);
        if (lane == 0) tmp0 = (float)i;
        float tmp1 = fminf(d1 + n1, prev1 + 1.0f);

        float sc0 = tmp0 - (float)j0;
        float sc1 = tmp1 - (float)j1;
        #pragma unroll
        for (int off = 1; off < 32; off <<= 1) {     // interleaved min-scans
            float a0 = __shfl_up_sync(FULL, sc0, off);
            float a1 = __shfl_up_sync(FULL, sc1, off);
            if (lane >= off) { sc0 = fminf(sc0, a0); sc1 = fminf(sc1, a1); }
        }
        float tot0 = __shfl_sync(FULL, sc0, 31);
        sc1 = fminf(sc1, tot0);
        float cur0 = sc0 + (float)j0;
        float cur1 = sc1 + (float)j1;

        float v0 = (j0 < len) ? cur0 : 3.0e38f;
        float v1 = (j1 < len) ? cur1 : 3.0e38f;
        float r = fminf(v0, v1);
        #pragma unroll
        for (int off = 16; off; off >>= 1)
            r = fminf(r, __shfl_xor_sync(FULL, r, off));

        unsigned b0 = __ballot_sync(FULL, v0 == r);
        unsigned b1 = __ballot_sync(FULL, v1 == r);
        if (lane == 0) {
            g_mask32[(b * PP + i) * 2 + 0] = b0;
            g_mask32[(b * PP + i) * 2 + 1] = b1;
        }
        prev0 = cur0; prev1 = cur1;
    }
    __threadfence();
    if (lane == 0) g_dp_done[b] = 1;
}

// ---------------------------------------------------------------------------
// One fused kernel:
//   blocks 0..31            : DP for batch b = blockIdx (wave-1 resident)
//   blocks 32..2079         : per-(b,i) row reduction (DRAM-bound), then
//                             brief spin for the DP bitmask, then closed-form
//                             two-value-softmax KL
//   last block to finish    : deterministic final scalar + state reset
// ---------------------------------------------------------------------------
__global__ void __launch_bounds__(256)
fused_kernel(const float* __restrict__ outputs,
             const int* __restrict__ syms,
             const int* __restrict__ targets,
             const void* __restrict__ mask,
             float* __restrict__ out) {
    const int tid = threadIdx.x;
    const int mode = mask_mode(mask);
    __shared__ int   targ[LL];
    __shared__ float sw[8];
    __shared__ float sh_hv[2];
    __shared__ int   sh_fl[2];
    __shared__ int   sh_win;
    __shared__ float pb[BB];

    if (blockIdx.x < BB) {
        // ---------------- DP role ----------------
        if (tid < 32) dp_warp(blockIdx.x, syms, targets, mask, mode);
    } else {
        // ---------------- reduce role ----------------
        const int blk = blockIdx.x - BB;         // 0..2047
        const int b = blk >> 6, i = blk & 63;

        // own-row mask length (cheap, avoids dependency on DP blocks)
        bool mb = (tid < LL) && mask_at(mask, mode, b * LL + tid);
        int len = __syncthreads_count(mb);

        if (i >= len) {
            if (tid == 0) g_loss[blk] = 0.0f;
        } else {
            const float* row = outputs + (size_t)blk * VV;
            if (tid < LL) targ[tid] = targets[b * LL + tid];

            // streaming full-row sum (the DRAM-bound part)
            const float4* r4 = (const float4*)row;   // 8000 float4
            float acc = 0.0f;
            #pragma unroll 4
            for (int idx = tid; idx < VV / 4; idx += 256) {
                float4 v = __ldcs(r4 + idx);
                acc += (v.x + v.y) + (v.z + v.w);
            }
            #pragma unroll
            for (int off = 16; off; off >>= 1)
                acc += __shfl_xor_sync(0xffffffffu, acc, off);
            if ((tid & 31) == 0) sw[tid >> 5] = acc;

            // DP for this batch is long done by now (wave-1, ~5us vs ~25us)
            if (tid == 0) { while (g_dp_done[b] == 0) { } }
            __syncthreads();
            __threadfence();

            if (tid < 64) {       // hit-set dedup + gather
                unsigned lo = g_mask32[blk * 2 + 0];
                unsigned hi = g_mask32[blk * 2 + 1];
                int j = tid;
                bool hit = (j < 32) ? ((lo >> j) & 1u) : ((hi >> (j - 32)) & 1u);
                float val = 0.0f; int flag = 0;
                if (hit) {
                    int c = targ[j];
                    bool first = true;
                    for (int k = 0; k < j; k++) {
                        bool hk = (k < 32) ? ((lo >> k) & 1u)
                                           : ((hi >> (k - 32)) & 1u);
                        if (hk && targ[k] == c) { first = false; break; }
                    }
                    if (first) { val = row[c]; flag = 1; }
                }
                #pragma unroll
                for (int off = 16; off; off >>= 1) {
                    val  += __shfl_xor_sync(0xffffffffu, val, off);
                    flag += __shfl_xor_sync(0xffffffffu, flag, off);
                }
                if ((tid & 31) == 0) { sh_hv[tid >> 5] = val; sh_fl[tid >> 5] = flag; }
            }
            __syncthreads();

            if (tid == 0) {
                float S_all = 0.0f;
                for (int k = 0; k < 8; k++) S_all += sw[k];
                float S_hit = sh_hv[0] + sh_hv[1];
                int   m     = sh_fl[0] + sh_fl[1];

                const float em1 = 0.36787944117144233f;  // e^-1
                float fm = (float)m;
                float Z  = fm + ((float)VV - fm) * em1;
                float ph = 1.0f / Z;
                float pm = em1 / Z;
                float ent = fm * ph * logf(ph) + ((float)VV - fm) * pm * logf(pm);
                g_loss[blk] = ent - (pm * S_all + (ph - pm) * S_hit);
            }
        }
    }

    // ---------------- ticket: last block does the final scalar ----------------
    __syncthreads();
    if (tid == 0) {
        __threadfence();                          // release my g_* writes
        unsigned old = atomicAdd(&g_ctr, 1u);
        sh_win = (old == NBLK - 1) ? 1 : 0;
    }
    __syncthreads();

    if (sh_win) {
        __threadfence();                          // acquire everyone's writes
        if (tid < BB) {
            float s = 0.0f;
            for (int i = 0; i < PP; i++) s += g_loss[tid * PP + i];
            pb[tid] = s / ((float)g_len[tid] + 1e-13f);
        }
        __syncthreads();
        if (tid == 0) {
            float acc = 0.0f, n = 0.0f;
            for (int k = 0; k < BB; k++) {
                acc += pb[k];
                if (g_len[k] > 0) n += 1.0f;
            }
            out[0] = acc / (n + 1e-13f);
            // reset state for the next graph replay
            g_ctr = 0;
            for (int k = 0; k < BB; k++) g_dp_done[k] = 0;
        }
    }
}

// ---------------------------------------------------------------------------
extern "C" void kernel_launch(void* const* d_in, const int* in_sizes, int n_in,
                              void* d_out, int out_size) {
    const float* outputs = (const float*)d_in[0];   // (B,P,V) f32 log-probs
    const int*   syms    = (const int*)d_in[1];     // (B,P) i32
    const int*   targets = (const int*)d_in[2];     // (B,L) i32
    const void*  mask    = d_in[3];                 // (B,L) bool-ish

    fused_kernel<<<NBLK, 256>>>(outputs, syms, targets, mask, (float*)d_out);
}